// round 11
// baseline (speedup 1.0000x reference)
#include <cuda_runtime.h>
#include <math.h>

#define B_DIM 256
#define N_DIM 256
#define D_DIM 512
#define MARGIN 0.5f
#define EPS_V 1e-6f
#define ROWS (B_DIM * N_DIM)           // 65536
#define BND ((size_t)ROWS * D_DIM)     // 33554432

// ---- scratch (device globals; no allocation allowed) ----
__device__ float g_dp[ROWS];
__device__ float g_dn[ROWS];
__device__ float g_loss_partial[B_DIM];
__device__ int   g_neg_idx[B_DIM];
__device__ int   g_pos_idx[B_DIM];
__device__ int   g_valid_neg[B_DIM];
__device__ int   g_valid_pos[B_DIM];
__device__ int   g_perm[2][B_DIM];   // batch visit order, sorted by source idx

// ============================================================
// Kernel 1: per-row L2 distances. Warp-per-row, streaming loads.
// ============================================================
__global__ __launch_bounds__(256) void dist_kernel(
    const float* __restrict__ anchor,
    const float* __restrict__ positive,
    const float* __restrict__ negative)
{
    const int row  = blockIdx.x * 8 + (threadIdx.x >> 5);
    const int lane = threadIdx.x & 31;

    const float4* a4 = (const float4*)(anchor   + (size_t)row * D_DIM);
    const float4* p4 = (const float4*)(positive + (size_t)row * D_DIM);
    const float4* n4 = (const float4*)(negative + (size_t)row * D_DIM);

    float4 av[4], pv[4], nv[4];
    #pragma unroll
    for (int i = 0; i < 4; i++) av[i] = __ldcs(&a4[lane + 32 * i]);
    #pragma unroll
    for (int i = 0; i < 4; i++) pv[i] = __ldcs(&p4[lane + 32 * i]);
    #pragma unroll
    for (int i = 0; i < 4; i++) nv[i] = __ldcs(&n4[lane + 32 * i]);

    float dp = 0.0f, dn = 0.0f;
    #pragma unroll
    for (int i = 0; i < 4; i++) {
        float x0 = av[i].x - pv[i].x + EPS_V, x1 = av[i].y - pv[i].y + EPS_V;
        float x2 = av[i].z - pv[i].z + EPS_V, x3 = av[i].w - pv[i].w + EPS_V;
        dp += x0*x0 + x1*x1 + x2*x2 + x3*x3;
        float y0 = av[i].x - nv[i].x + EPS_V, y1 = av[i].y - nv[i].y + EPS_V;
        float y2 = av[i].z - nv[i].z + EPS_V, y3 = av[i].w - nv[i].w + EPS_V;
        dn += y0*y0 + y1*y1 + y2*y2 + y3*y3;
    }

    #pragma unroll
    for (int off = 16; off > 0; off >>= 1) {
        dp += __shfl_xor_sync(0xFFFFFFFFu, dp, off);
        dn += __shfl_xor_sync(0xFFFFFFFFu, dn, off);
    }

    if (lane == 0) {
        g_dp[row] = sqrtf(dp);
        g_dn[row] = sqrtf(dn);
    }
}

// ============================================================
// Kernel 2: per-batch hard mining + loss partials + valid flags.
// ============================================================
__global__ __launch_bounds__(256) void mine_kernel(float* __restrict__ out)
{
    const int b = blockIdx.x;
    const int n = threadIdx.x;

    const float dp = g_dp[b * N_DIM + n];
    const float dn = g_dn[b * N_DIM + n];

    const bool mask_neg = (dp - dn + MARGIN) > 0.0f;
    const bool mask_pos = (dn - dp + MARGIN) > 0.0f;

    __shared__ float s_sn[N_DIM]; __shared__ int s_in[N_DIM];
    __shared__ float s_sp[N_DIM]; __shared__ int s_ip[N_DIM];
    __shared__ float s_l [N_DIM];

    s_sn[n] = mask_neg ? dn : -INFINITY;  s_in[n] = n;
    s_sp[n] = mask_pos ? dp :  INFINITY;  s_ip[n] = n;
    s_l [n] = fmaxf(0.0f, MARGIN + dp - dn);
    __syncthreads();

    for (int off = N_DIM / 2; off > 0; off >>= 1) {
        if (n < off) {
            float so = s_sn[n + off]; int io = s_in[n + off];
            if (so > s_sn[n] || (so == s_sn[n] && io < s_in[n])) {
                s_sn[n] = so; s_in[n] = io;
            }
            float qo = s_sp[n + off]; int jo = s_ip[n + off];
            if (qo < s_sp[n] || (qo == s_sp[n] && jo < s_ip[n])) {
                s_sp[n] = qo; s_ip[n] = jo;
            }
            s_l[n] += s_l[n + off];
        }
        __syncthreads();
    }

    if (n == 0) {
        const int vn = (s_sn[0] > -INFINITY) ? 1 : 0;
        const int vp = (s_sp[0] <  INFINITY) ? 1 : 0;
        g_neg_idx[b] = s_in[0];
        g_pos_idx[b] = s_ip[0];
        g_valid_neg[b] = vn;
        g_valid_pos[b] = vp;
        g_loss_partial[b] = s_l[0];
        out[1 + 2 * BND + b]         = (float)vn;
        out[1 + 2 * BND + B_DIM + b] = (float)vp;
    }
}

// ============================================================
// Kernel 3: finalize. Block 0: loss sum + perm for side 0.
// Block 1: perm for side 1.
// perm = stable counting sort of batches by source index (valid first,
// invalid appended). Valid placement uses per-bin atomics (order within
// a bin is scheduling-only; output bytes unaffected).
// ============================================================
__global__ __launch_bounds__(256) void finalize_kernel(float* __restrict__ out)
{
    const int side = blockIdx.x;        // 0 = neg, 1 = pos
    const int t = threadIdx.x;

    // ---- loss (block 0 only) ----
    __shared__ float s_l[B_DIM];
    if (side == 0) {
        s_l[t] = g_loss_partial[t];
        __syncthreads();
        for (int off = B_DIM / 2; off > 0; off >>= 1) {
            if (t < off) s_l[t] += s_l[t + off];
            __syncthreads();
        }
        if (t == 0) out[0] = s_l[0] * (1.0f / (float)(B_DIM * N_DIM));
    }

    // ---- perm via counting sort ----
    const int* idx = (side == 0) ? g_neg_idx   : g_pos_idx;
    const int* val = (side == 0) ? g_valid_neg : g_valid_pos;

    __shared__ int s_cnt[B_DIM];
    __shared__ int s_a[B_DIM];
    __shared__ int s_b[B_DIM];
    __shared__ int s_cur[B_DIM];
    __shared__ int s_nvalid;

    const int my_idx = idx[t];
    const int my_val = val[t];

    s_cnt[t] = 0;
    __syncthreads();
    if (my_val) atomicAdd(&s_cnt[my_idx], 1);
    __syncthreads();

    {
        const int v = s_cnt[t];
        s_a[t] = v;
        __syncthreads();
        int* cur = s_a; int* nxt = s_b;
        for (int d = 1; d < B_DIM; d <<= 1) {
            nxt[t] = (t >= d) ? (cur[t] + cur[t - d]) : cur[t];
            __syncthreads();
            int* tmp = cur; cur = nxt; nxt = tmp;
        }
        s_cur[t] = cur[t] - v;           // exclusive bin offset
        if (t == B_DIM - 1) s_nvalid = cur[t];
        __syncthreads();
    }

    if (my_val) {
        int p = atomicAdd(&s_cur[my_idx], 1);
        g_perm[side][p] = t;
    }
    __syncthreads();

    {
        const int inv = my_val ? 0 : 1;
        s_a[t] = inv;
        __syncthreads();
        int* cur = s_a; int* nxt = s_b;
        for (int d = 1; d < B_DIM; d <<= 1) {
            nxt[t] = (t >= d) ? (cur[t] + cur[t - d]) : cur[t];
            __syncthreads();
            int* tmp = cur; cur = nxt; nxt = tmp;
        }
        if (inv) g_perm[side][s_nvalid + cur[t] - 1] = t;
    }
}

// ============================================================
// Kernel 4: gather with source-sorted scheduling + shuffle realignment.
// Block = (batch-position, n, side); dest batch = g_perm[side][pos].
// Thread t does ONE aligned LDG.128: L[t] = src[4t..4t+3] (coalesced,
// 4 L1 wavefronts/warp = compulsory). The +3-shifted store vector
// {L[t].w, L[t+1].xyz} is built via shfl_down(1); warp boundaries and
// the row head come from a 4-entry smem buffer. Thread 127 writes the
// head scalars (0,1,2) and tail (511).
// ============================================================
__global__ __launch_bounds__(128) void gather_kernel(
    const float* __restrict__ positive,
    const float* __restrict__ negative,
    float* __restrict__ out)
{
    const int pos  = blockIdx.x;
    const int n    = blockIdx.y;
    const int side = blockIdx.z;
    const int t    = threadIdx.x;
    const int lane = t & 31;
    const int wid  = t >> 5;

    const int b = g_perm[side][pos];
    const int valid = (side == 0) ? g_valid_neg[b] : g_valid_pos[b];
    const int sidx  = (side == 0) ? g_neg_idx[b]   : g_pos_idx[b];

    const float* __restrict__ src =
        ((side == 0) ? negative : positive) + ((size_t)sidx * N_DIM + n) * D_DIM;
    float* __restrict__ dst =
        out + 1 + (side ? BND : 0) + ((size_t)b * N_DIM + n) * D_DIM;

    __shared__ float3 s_bound[4];   // L[0], L[32], L[64], L[96] .xyz

    float4 L = make_float4(0.f, 0.f, 0.f, 0.f);
    if (valid) L = __ldg((const float4*)src + t);

    if (lane == 0) s_bound[wid] = make_float3(L.x, L.y, L.z);
    __syncthreads();

    float nx = __shfl_down_sync(0xFFFFFFFFu, L.x, 1);
    float ny = __shfl_down_sync(0xFFFFFFFFu, L.y, 1);
    float nz = __shfl_down_sync(0xFFFFFFFFu, L.z, 1);
    if (lane == 31 && wid < 3) {
        float3 bd = s_bound[wid + 1];
        nx = bd.x; ny = bd.y; nz = bd.z;
    }

    if (t < 127) {
        // dst + 3 + 4t is 16B-aligned (dst = out + 1 + 512*row)
        __stcs((float4*)(dst + 3 + 4 * t), make_float4(L.w, nx, ny, nz));
    } else {
        float3 h = s_bound[0];
        dst[0] = h.x; dst[1] = h.y; dst[2] = h.z;
        dst[511] = L.w;
    }
}

// ============================================================
extern "C" void kernel_launch(void* const* d_in, const int* in_sizes, int n_in,
                              void* d_out, int out_size)
{
    const float* anchor   = (const float*)d_in[0];
    const float* positive = (const float*)d_in[1];
    const float* negative = (const float*)d_in[2];
    float* out = (float*)d_out;

    dist_kernel    <<<ROWS / 8, 256>>>(anchor, positive, negative);
    mine_kernel    <<<B_DIM, 256>>>(out);
    finalize_kernel<<<2, 256>>>(out);

    dim3 ggrid(B_DIM, N_DIM, 2);
    gather_kernel<<<ggrid, 128>>>(positive, negative, out);
}

// round 12
// speedup vs baseline: 1.1041x; 1.1041x over previous
#include <cuda_runtime.h>
#include <math.h>

#define B_DIM 256
#define N_DIM 256
#define D_DIM 512
#define MARGIN 0.5f
#define EPS_V 1e-6f
#define ROWS (B_DIM * N_DIM)           // 65536
#define BND ((size_t)ROWS * D_DIM)     // 33554432

// ---- scratch (device globals; no allocation allowed) ----
__device__ float g_dp[ROWS];
__device__ float g_dn[ROWS];
__device__ float g_loss_partial[B_DIM];
__device__ int   g_neg_idx[B_DIM];
__device__ int   g_pos_idx[B_DIM];
__device__ int   g_valid_neg[B_DIM];
__device__ int   g_valid_pos[B_DIM];
__device__ int   g_perm[2][B_DIM];   // batch visit order, sorted by source idx

// ============================================================
// Kernel 1: per-row L2 distances. Warp-per-row, streaming loads.
// ============================================================
__global__ __launch_bounds__(256) void dist_kernel(
    const float* __restrict__ anchor,
    const float* __restrict__ positive,
    const float* __restrict__ negative)
{
    const int row  = blockIdx.x * 8 + (threadIdx.x >> 5);
    const int lane = threadIdx.x & 31;

    const float4* a4 = (const float4*)(anchor   + (size_t)row * D_DIM);
    const float4* p4 = (const float4*)(positive + (size_t)row * D_DIM);
    const float4* n4 = (const float4*)(negative + (size_t)row * D_DIM);

    float4 av[4], pv[4], nv[4];
    #pragma unroll
    for (int i = 0; i < 4; i++) av[i] = __ldcs(&a4[lane + 32 * i]);
    #pragma unroll
    for (int i = 0; i < 4; i++) pv[i] = __ldcs(&p4[lane + 32 * i]);
    #pragma unroll
    for (int i = 0; i < 4; i++) nv[i] = __ldcs(&n4[lane + 32 * i]);

    float dp = 0.0f, dn = 0.0f;
    #pragma unroll
    for (int i = 0; i < 4; i++) {
        float x0 = av[i].x - pv[i].x + EPS_V, x1 = av[i].y - pv[i].y + EPS_V;
        float x2 = av[i].z - pv[i].z + EPS_V, x3 = av[i].w - pv[i].w + EPS_V;
        dp += x0*x0 + x1*x1 + x2*x2 + x3*x3;
        float y0 = av[i].x - nv[i].x + EPS_V, y1 = av[i].y - nv[i].y + EPS_V;
        float y2 = av[i].z - nv[i].z + EPS_V, y3 = av[i].w - nv[i].w + EPS_V;
        dn += y0*y0 + y1*y1 + y2*y2 + y3*y3;
    }

    #pragma unroll
    for (int off = 16; off > 0; off >>= 1) {
        dp += __shfl_xor_sync(0xFFFFFFFFu, dp, off);
        dn += __shfl_xor_sync(0xFFFFFFFFu, dn, off);
    }

    if (lane == 0) {
        g_dp[row] = sqrtf(dp);
        g_dn[row] = sqrtf(dn);
    }
}

// ============================================================
// Kernel 2: per-batch hard mining + loss partials + valid flags.
// ============================================================
__global__ __launch_bounds__(256) void mine_kernel(float* __restrict__ out)
{
    const int b = blockIdx.x;
    const int n = threadIdx.x;

    const float dp = g_dp[b * N_DIM + n];
    const float dn = g_dn[b * N_DIM + n];

    const bool mask_neg = (dp - dn + MARGIN) > 0.0f;
    const bool mask_pos = (dn - dp + MARGIN) > 0.0f;

    __shared__ float s_sn[N_DIM]; __shared__ int s_in[N_DIM];
    __shared__ float s_sp[N_DIM]; __shared__ int s_ip[N_DIM];
    __shared__ float s_l [N_DIM];

    s_sn[n] = mask_neg ? dn : -INFINITY;  s_in[n] = n;
    s_sp[n] = mask_pos ? dp :  INFINITY;  s_ip[n] = n;
    s_l [n] = fmaxf(0.0f, MARGIN + dp - dn);
    __syncthreads();

    for (int off = N_DIM / 2; off > 0; off >>= 1) {
        if (n < off) {
            float so = s_sn[n + off]; int io = s_in[n + off];
            if (so > s_sn[n] || (so == s_sn[n] && io < s_in[n])) {
                s_sn[n] = so; s_in[n] = io;
            }
            float qo = s_sp[n + off]; int jo = s_ip[n + off];
            if (qo < s_sp[n] || (qo == s_sp[n] && jo < s_ip[n])) {
                s_sp[n] = qo; s_ip[n] = jo;
            }
            s_l[n] += s_l[n + off];
        }
        __syncthreads();
    }

    if (n == 0) {
        const int vn = (s_sn[0] > -INFINITY) ? 1 : 0;
        const int vp = (s_sp[0] <  INFINITY) ? 1 : 0;
        g_neg_idx[b] = s_in[0];
        g_pos_idx[b] = s_ip[0];
        g_valid_neg[b] = vn;
        g_valid_pos[b] = vp;
        g_loss_partial[b] = s_l[0];
        out[1 + 2 * BND + b]         = (float)vn;
        out[1 + 2 * BND + B_DIM + b] = (float)vp;
    }
}

// ============================================================
// Kernel 3: finalize. Block 0: loss sum + perm for side 0.
// Block 1: perm for side 1.
// perm = stable counting sort of batches by source index (valid first,
// invalid appended). Valid placement uses per-bin atomics (order within
// a bin is scheduling-only; output bytes unaffected).
// ============================================================
__global__ __launch_bounds__(256) void finalize_kernel(float* __restrict__ out)
{
    const int side = blockIdx.x;        // 0 = neg, 1 = pos
    const int t = threadIdx.x;

    __shared__ float s_l[B_DIM];
    if (side == 0) {
        s_l[t] = g_loss_partial[t];
        __syncthreads();
        for (int off = B_DIM / 2; off > 0; off >>= 1) {
            if (t < off) s_l[t] += s_l[t + off];
            __syncthreads();
        }
        if (t == 0) out[0] = s_l[0] * (1.0f / (float)(B_DIM * N_DIM));
    }

    const int* idx = (side == 0) ? g_neg_idx   : g_pos_idx;
    const int* val = (side == 0) ? g_valid_neg : g_valid_pos;

    __shared__ int s_cnt[B_DIM];
    __shared__ int s_a[B_DIM];
    __shared__ int s_b[B_DIM];
    __shared__ int s_cur[B_DIM];
    __shared__ int s_nvalid;

    const int my_idx = idx[t];
    const int my_val = val[t];

    s_cnt[t] = 0;
    __syncthreads();
    if (my_val) atomicAdd(&s_cnt[my_idx], 1);
    __syncthreads();

    {
        const int v = s_cnt[t];
        s_a[t] = v;
        __syncthreads();
        int* cur = s_a; int* nxt = s_b;
        for (int d = 1; d < B_DIM; d <<= 1) {
            nxt[t] = (t >= d) ? (cur[t] + cur[t - d]) : cur[t];
            __syncthreads();
            int* tmp = cur; cur = nxt; nxt = tmp;
        }
        s_cur[t] = cur[t] - v;           // exclusive bin offset
        if (t == B_DIM - 1) s_nvalid = cur[t];
        __syncthreads();
    }

    if (my_val) {
        int p = atomicAdd(&s_cur[my_idx], 1);
        g_perm[side][p] = t;
    }
    __syncthreads();

    {
        const int inv = my_val ? 0 : 1;
        s_a[t] = inv;
        __syncthreads();
        int* cur = s_a; int* nxt = s_b;
        for (int d = 1; d < B_DIM; d <<= 1) {
            nxt[t] = (t >= d) ? (cur[t] + cur[t - d]) : cur[t];
            __syncthreads();
            int* tmp = cur; cur = nxt; nxt = tmp;
        }
        if (inv) g_perm[side][s_nvalid + cur[t] - 1] = t;
    }
}

// ============================================================
// Kernel 4: gather, 4 rows per block (MLP=4) + sorted scheduling +
// shuffle realignment.
// Block = (batch-position, n-group of 4, side); dest batch =
// g_perm[side][pos]. Thread t issues 4 independent aligned LDG.128
// (rows n0..n0+3, 2KB apart -> 8KB contiguous per block), then per row
// builds the +3-shifted store vector {L.w, next.xyz} via shfl_down(1),
// with warp-boundary/head patches from smem. Thread 127 writes head
// scalars (0,1,2) and tail (511) of each row.
// ============================================================
__global__ __launch_bounds__(128) void gather_kernel(
    const float* __restrict__ positive,
    const float* __restrict__ negative,
    float* __restrict__ out)
{
    const int pos  = blockIdx.x;
    const int n0   = blockIdx.y * 4;
    const int side = blockIdx.z;
    const int t    = threadIdx.x;
    const int lane = t & 31;
    const int wid  = t >> 5;

    const int b = g_perm[side][pos];
    const int valid = (side == 0) ? g_valid_neg[b] : g_valid_pos[b];
    const int sidx  = (side == 0) ? g_neg_idx[b]   : g_pos_idx[b];

    const float4* __restrict__ src4 = (const float4*)(
        ((side == 0) ? negative : positive)
        + ((size_t)sidx * N_DIM + n0) * D_DIM);
    float* __restrict__ dst0 =
        out + 1 + (side ? BND : 0) + ((size_t)b * N_DIM + n0) * D_DIM;

    __shared__ float3 s_bound[4][4];   // [row][warp]: L at lanes 0/32/64/96

    // 4 independent loads in flight (rows are 128 float4 = 2KB apart)
    float4 L[4];
    #pragma unroll
    for (int r = 0; r < 4; r++) L[r] = make_float4(0.f, 0.f, 0.f, 0.f);
    if (valid) {
        #pragma unroll
        for (int r = 0; r < 4; r++) L[r] = __ldg(src4 + r * 128 + t);
    }

    if (lane == 0) {
        #pragma unroll
        for (int r = 0; r < 4; r++)
            s_bound[r][wid] = make_float3(L[r].x, L[r].y, L[r].z);
    }
    __syncthreads();

    #pragma unroll
    for (int r = 0; r < 4; r++) {
        float nx = __shfl_down_sync(0xFFFFFFFFu, L[r].x, 1);
        float ny = __shfl_down_sync(0xFFFFFFFFu, L[r].y, 1);
        float nz = __shfl_down_sync(0xFFFFFFFFu, L[r].z, 1);
        if (lane == 31 && wid < 3) {
            float3 bd = s_bound[r][wid + 1];
            nx = bd.x; ny = bd.y; nz = bd.z;
        }
        float* dst = dst0 + r * D_DIM;
        if (t < 127) {
            // dst + 3 + 4t is 16B-aligned (dst = out + 1 + 512*row)
            __stcs((float4*)(dst + 3 + 4 * t), make_float4(L[r].w, nx, ny, nz));
        } else {
            float3 h = s_bound[r][0];
            dst[0] = h.x; dst[1] = h.y; dst[2] = h.z;
            dst[511] = L[r].w;
        }
    }
}

// ============================================================
extern "C" void kernel_launch(void* const* d_in, const int* in_sizes, int n_in,
                              void* d_out, int out_size)
{
    const float* anchor   = (const float*)d_in[0];
    const float* positive = (const float*)d_in[1];
    const float* negative = (const float*)d_in[2];
    float* out = (float*)d_out;

    dist_kernel    <<<ROWS / 8, 256>>>(anchor, positive, negative);
    mine_kernel    <<<B_DIM, 256>>>(out);
    finalize_kernel<<<2, 256>>>(out);

    dim3 ggrid(B_DIM, N_DIM / 4, 2);
    gather_kernel<<<ggrid, 128>>>(positive, negative, out);
}

// round 13
// speedup vs baseline: 1.1049x; 1.0007x over previous
#include <cuda_runtime.h>
#include <math.h>

#define B_DIM 256
#define N_DIM 256
#define D_DIM 512
#define MARGIN 0.5f
#define EPS_V 1e-6f
#define ROWS (B_DIM * N_DIM)           // 65536
#define BND ((size_t)ROWS * D_DIM)     // 33554432

// ---- scratch (device globals; no allocation allowed) ----
__device__ float g_dp[ROWS];
__device__ float g_dn[ROWS];
__device__ float g_loss_partial[B_DIM];
__device__ int   g_neg_idx[B_DIM];
__device__ int   g_pos_idx[B_DIM];
__device__ int   g_valid_neg[B_DIM];
__device__ int   g_valid_pos[B_DIM];
__device__ int   g_perm[2][B_DIM];   // batch visit order, sorted by source idx

// ============================================================
// Kernel 1: per-row L2 distances. Warp-per-row, streaming loads.
// ============================================================
__global__ __launch_bounds__(256) void dist_kernel(
    const float* __restrict__ anchor,
    const float* __restrict__ positive,
    const float* __restrict__ negative)
{
    const int row  = blockIdx.x * 8 + (threadIdx.x >> 5);
    const int lane = threadIdx.x & 31;

    const float4* a4 = (const float4*)(anchor   + (size_t)row * D_DIM);
    const float4* p4 = (const float4*)(positive + (size_t)row * D_DIM);
    const float4* n4 = (const float4*)(negative + (size_t)row * D_DIM);

    float4 av[4], pv[4], nv[4];
    #pragma unroll
    for (int i = 0; i < 4; i++) av[i] = __ldcs(&a4[lane + 32 * i]);
    #pragma unroll
    for (int i = 0; i < 4; i++) pv[i] = __ldcs(&p4[lane + 32 * i]);
    #pragma unroll
    for (int i = 0; i < 4; i++) nv[i] = __ldcs(&n4[lane + 32 * i]);

    float dp = 0.0f, dn = 0.0f;
    #pragma unroll
    for (int i = 0; i < 4; i++) {
        float x0 = av[i].x - pv[i].x + EPS_V, x1 = av[i].y - pv[i].y + EPS_V;
        float x2 = av[i].z - pv[i].z + EPS_V, x3 = av[i].w - pv[i].w + EPS_V;
        dp += x0*x0 + x1*x1 + x2*x2 + x3*x3;
        float y0 = av[i].x - nv[i].x + EPS_V, y1 = av[i].y - nv[i].y + EPS_V;
        float y2 = av[i].z - nv[i].z + EPS_V, y3 = av[i].w - nv[i].w + EPS_V;
        dn += y0*y0 + y1*y1 + y2*y2 + y3*y3;
    }

    #pragma unroll
    for (int off = 16; off > 0; off >>= 1) {
        dp += __shfl_xor_sync(0xFFFFFFFFu, dp, off);
        dn += __shfl_xor_sync(0xFFFFFFFFu, dn, off);
    }

    if (lane == 0) {
        g_dp[row] = sqrtf(dp);
        g_dn[row] = sqrtf(dn);
    }
}

// ============================================================
// Kernel 2: per-batch hard mining + loss partials + valid flags.
// ============================================================
__global__ __launch_bounds__(256) void mine_kernel(float* __restrict__ out)
{
    const int b = blockIdx.x;
    const int n = threadIdx.x;

    const float dp = g_dp[b * N_DIM + n];
    const float dn = g_dn[b * N_DIM + n];

    const bool mask_neg = (dp - dn + MARGIN) > 0.0f;
    const bool mask_pos = (dn - dp + MARGIN) > 0.0f;

    __shared__ float s_sn[N_DIM]; __shared__ int s_in[N_DIM];
    __shared__ float s_sp[N_DIM]; __shared__ int s_ip[N_DIM];
    __shared__ float s_l [N_DIM];

    s_sn[n] = mask_neg ? dn : -INFINITY;  s_in[n] = n;
    s_sp[n] = mask_pos ? dp :  INFINITY;  s_ip[n] = n;
    s_l [n] = fmaxf(0.0f, MARGIN + dp - dn);
    __syncthreads();

    for (int off = N_DIM / 2; off > 0; off >>= 1) {
        if (n < off) {
            float so = s_sn[n + off]; int io = s_in[n + off];
            if (so > s_sn[n] || (so == s_sn[n] && io < s_in[n])) {
                s_sn[n] = so; s_in[n] = io;
            }
            float qo = s_sp[n + off]; int jo = s_ip[n + off];
            if (qo < s_sp[n] || (qo == s_sp[n] && jo < s_ip[n])) {
                s_sp[n] = qo; s_ip[n] = jo;
            }
            s_l[n] += s_l[n + off];
        }
        __syncthreads();
    }

    if (n == 0) {
        const int vn = (s_sn[0] > -INFINITY) ? 1 : 0;
        const int vp = (s_sp[0] <  INFINITY) ? 1 : 0;
        g_neg_idx[b] = s_in[0];
        g_pos_idx[b] = s_ip[0];
        g_valid_neg[b] = vn;
        g_valid_pos[b] = vp;
        g_loss_partial[b] = s_l[0];
        out[1 + 2 * BND + b]         = (float)vn;
        out[1 + 2 * BND + B_DIM + b] = (float)vp;
    }
}

// ============================================================
// Kernel 3: finalize. Block 0: loss sum + perm for side 0.
// Block 1: perm for side 1.
// perm = stable counting sort of batches by source index (valid first,
// invalid appended). Valid placement uses per-bin atomics (order within
// a bin is scheduling-only; output bytes unaffected).
// ============================================================
__global__ __launch_bounds__(256) void finalize_kernel(float* __restrict__ out)
{
    const int side = blockIdx.x;        // 0 = neg, 1 = pos
    const int t = threadIdx.x;

    __shared__ float s_l[B_DIM];
    if (side == 0) {
        s_l[t] = g_loss_partial[t];
        __syncthreads();
        for (int off = B_DIM / 2; off > 0; off >>= 1) {
            if (t < off) s_l[t] += s_l[t + off];
            __syncthreads();
        }
        if (t == 0) out[0] = s_l[0] * (1.0f / (float)(B_DIM * N_DIM));
    }

    const int* idx = (side == 0) ? g_neg_idx   : g_pos_idx;
    const int* val = (side == 0) ? g_valid_neg : g_valid_pos;

    __shared__ int s_cnt[B_DIM];
    __shared__ int s_a[B_DIM];
    __shared__ int s_b[B_DIM];
    __shared__ int s_cur[B_DIM];
    __shared__ int s_nvalid;

    const int my_idx = idx[t];
    const int my_val = val[t];

    s_cnt[t] = 0;
    __syncthreads();
    if (my_val) atomicAdd(&s_cnt[my_idx], 1);
    __syncthreads();

    {
        const int v = s_cnt[t];
        s_a[t] = v;
        __syncthreads();
        int* cur = s_a; int* nxt = s_b;
        for (int d = 1; d < B_DIM; d <<= 1) {
            nxt[t] = (t >= d) ? (cur[t] + cur[t - d]) : cur[t];
            __syncthreads();
            int* tmp = cur; cur = nxt; nxt = tmp;
        }
        s_cur[t] = cur[t] - v;           // exclusive bin offset
        if (t == B_DIM - 1) s_nvalid = cur[t];
        __syncthreads();
    }

    if (my_val) {
        int p = atomicAdd(&s_cur[my_idx], 1);
        g_perm[side][p] = t;
    }
    __syncthreads();

    {
        const int inv = my_val ? 0 : 1;
        s_a[t] = inv;
        __syncthreads();
        int* cur = s_a; int* nxt = s_b;
        for (int d = 1; d < B_DIM; d <<= 1) {
            nxt[t] = (t >= d) ? (cur[t] + cur[t - d]) : cur[t];
            __syncthreads();
            int* tmp = cur; cur = nxt; nxt = tmp;
        }
        if (inv) g_perm[side][s_nvalid + cur[t] - 1] = t;
    }
}

// ============================================================
// Kernel 4: gather, 8 rows per block (MLP=8) + sorted scheduling +
// shuffle realignment.
// Block = (batch-position, n-group of 8, side); dest batch =
// g_perm[side][pos]. Thread t issues 8 independent aligned LDG.128
// (rows n0..n0+7, 2KB apart -> 16KB contiguous per block), then per row
// builds the +3-shifted store vector {L.w, next.xyz} via shfl_down(1),
// with warp-boundary/head patches from smem. Thread 127 writes head
// scalars (0,1,2) and tail (511) of each row.
// ============================================================
#define GROWS 8
__global__ __launch_bounds__(128) void gather_kernel(
    const float* __restrict__ positive,
    const float* __restrict__ negative,
    float* __restrict__ out)
{
    const int pos  = blockIdx.x;
    const int n0   = blockIdx.y * GROWS;
    const int side = blockIdx.z;
    const int t    = threadIdx.x;
    const int lane = t & 31;
    const int wid  = t >> 5;

    const int b = g_perm[side][pos];
    const int valid = (side == 0) ? g_valid_neg[b] : g_valid_pos[b];
    const int sidx  = (side == 0) ? g_neg_idx[b]   : g_pos_idx[b];

    const float4* __restrict__ src4 = (const float4*)(
        ((side == 0) ? negative : positive)
        + ((size_t)sidx * N_DIM + n0) * D_DIM);
    float* __restrict__ dst0 =
        out + 1 + (side ? BND : 0) + ((size_t)b * N_DIM + n0) * D_DIM;

    __shared__ float3 s_bound[GROWS][4];   // [row][warp]: L at lanes 0/32/64/96

    // 8 independent loads in flight (rows are 128 float4 = 2KB apart)
    float4 L[GROWS];
    #pragma unroll
    for (int r = 0; r < GROWS; r++) L[r] = make_float4(0.f, 0.f, 0.f, 0.f);
    if (valid) {
        #pragma unroll
        for (int r = 0; r < GROWS; r++) L[r] = __ldg(src4 + r * 128 + t);
    }

    if (lane == 0) {
        #pragma unroll
        for (int r = 0; r < GROWS; r++)
            s_bound[r][wid] = make_float3(L[r].x, L[r].y, L[r].z);
    }
    __syncthreads();

    #pragma unroll
    for (int r = 0; r < GROWS; r++) {
        float nx = __shfl_down_sync(0xFFFFFFFFu, L[r].x, 1);
        float ny = __shfl_down_sync(0xFFFFFFFFu, L[r].y, 1);
        float nz = __shfl_down_sync(0xFFFFFFFFu, L[r].z, 1);
        if (lane == 31 && wid < 3) {
            float3 bd = s_bound[r][wid + 1];
            nx = bd.x; ny = bd.y; nz = bd.z;
        }
        float* dst = dst0 + r * D_DIM;
        if (t < 127) {
            // dst + 3 + 4t is 16B-aligned (dst = out + 1 + 512*row)
            __stcs((float4*)(dst + 3 + 4 * t), make_float4(L[r].w, nx, ny, nz));
        } else {
            float3 h = s_bound[r][0];
            dst[0] = h.x; dst[1] = h.y; dst[2] = h.z;
            dst[511] = L[r].w;
        }
    }
}

// ============================================================
extern "C" void kernel_launch(void* const* d_in, const int* in_sizes, int n_in,
                              void* d_out, int out_size)
{
    const float* anchor   = (const float*)d_in[0];
    const float* positive = (const float*)d_in[1];
    const float* negative = (const float*)d_in[2];
    float* out = (float*)d_out;

    dist_kernel    <<<ROWS / 8, 256>>>(anchor, positive, negative);
    mine_kernel    <<<B_DIM, 256>>>(out);
    finalize_kernel<<<2, 256>>>(out);

    dim3 ggrid(B_DIM, N_DIM / GROWS, 2);
    gather_kernel<<<ggrid, 128>>>(positive, negative, out);
}